// round 5
// baseline (speedup 1.0000x reference)
#include <cuda_runtime.h>
#include <cuda_fp16.h>
#include <math.h>

#define BB 8
#define SS 4096
#define DD 768
#define MM 64
#define FF 3072
#define HH 12
#define HD 64
#define EPSF 1e-5f

typedef unsigned long long ull;

__device__ __forceinline__ ull pk2(float lo, float hi) {
    ull r;
    asm("mov.b64 %0, {%1, %2};" : "=l"(r) : "f"(lo), "f"(hi));
    return r;
}
__device__ __forceinline__ void upk2(ull v, float& lo, float& hi) {
    asm("mov.b64 {%0, %1}, %2;" : "=f"(lo), "=f"(hi) : "l"(v));
}
#define FMA2(a, x, y) asm("fma.rn.f32x2 %0, %1, %2, %0;" : "+l"(a) : "l"(x), "l"(y))

// ---------------- scratch -----------------------------------------------------
__device__ float  g_sl[MM * DD];
__device__ __half g_xn[BB * SS * DD];           // rms-normed x (fp16)
__device__ float  g_rn[BB * SS];
__device__ __half g_lh[(size_t)BB * HH * MM * SS];  // E = exp(logit - bmax[m]), fp16
__device__ float  g_rsum[BB * HH * MM];         // sum_s E  (atomically built)
__device__ float  g_bmax[MM];
__device__ float  g_cm[MM];                     // e^{bmax[m]}
__device__ float  g_y[BB * MM * DD];
__device__ float  g_hid[(size_t)BB * MM * FF];
__device__ float  g_y2[BB * MM * DD];

// ---------------- K0: slots + bmax/cm + zero rsum -------------------------------
__global__ void k_slots(const float* __restrict__ slots, const float* __restrict__ scale) {
    int m = blockIdx.x, tid = threadIdx.x;
    __shared__ float red[8];
    float ss = 0.f;
    for (int i = tid; i < DD; i += 256) { float v = slots[m * DD + i]; ss += v * v; }
    for (int o = 16; o; o >>= 1) ss += __shfl_down_sync(~0u, ss, o);
    if ((tid & 31) == 0) red[tid >> 5] = ss;
    __syncthreads();
    if (tid == 0) { float s = 0; for (int i = 0; i < 8; i++) s += red[i]; red[0] = s; }
    __syncthreads();
    float inv = scale[m] / fmaxf(sqrtf(red[0]), EPSF);
    for (int i = tid; i < DD; i += 256) g_sl[m * DD + i] = slots[m * DD + i] * inv;
    if (tid == 0) {
        float bm = fabsf(scale[m]);
        g_bmax[m] = bm;
        g_cm[m] = expf(bm);
    }
    // zero rsum (6144 floats over 64 blocks x 256 threads)
    for (int i = m * 256 + tid; i < BB * HH * MM; i += MM * 256) g_rsum[i] = 0.f;
}

// ---------------- K1: rmsnorm + l2, warp-per-token, fp16 out --------------------
__global__ void __launch_bounds__(256) k_norm(const float* __restrict__ x,
                                              const float* __restrict__ nw) {
    int t = blockIdx.x * 8 + (threadIdx.x >> 5);
    int lane = threadIdx.x & 31;
    const float4* xr = (const float4*)(x + (size_t)t * DD);
    const float4* wr = (const float4*)nw;
    float4 v[6];
    float ss = 0.f;
#pragma unroll
    for (int j = 0; j < 6; j++) {
        v[j] = xr[lane + 32 * j];
        ss += v[j].x * v[j].x + v[j].y * v[j].y + v[j].z * v[j].z + v[j].w * v[j].w;
    }
#pragma unroll
    for (int o = 16; o; o >>= 1) ss += __shfl_xor_sync(~0u, ss, o);
    float rstd = rsqrtf(ss / (float)DD + EPSF);
    __half* xo = g_xn + (size_t)t * DD;
    float s2 = 0.f;
#pragma unroll
    for (int j = 0; j < 6; j++) {
        float4 w = wr[lane + 32 * j];
        float4 a;
        a.x = v[j].x * rstd * w.x; a.y = v[j].y * rstd * w.y;
        a.z = v[j].z * rstd * w.z; a.w = v[j].w * rstd * w.w;
        s2 += a.x * a.x + a.y * a.y + a.z * a.z + a.w * a.w;
        __half2 h0 = __float22half2_rn(make_float2(a.x, a.y));
        __half2 h1 = __float22half2_rn(make_float2(a.z, a.w));
        uint2 u;
        u.x = *(unsigned*)&h0; u.y = *(unsigned*)&h1;
        *(uint2*)(xo + (lane + 32 * j) * 4) = u;
    }
#pragma unroll
    for (int o = 16; o; o >>= 1) s2 += __shfl_xor_sync(~0u, s2, o);
    if (lane == 0) g_rn[t] = 1.f / fmaxf(sqrtf(s2), EPSF);
}

// ---------------- K2: logits -> E = exp(dot - bmax), + row sums ------------------
__global__ void __launch_bounds__(128) k_logits() {
    int tid = threadIdx.x;
    int t0 = blockIdx.x * 256 + tid;
    int h = blockIdx.y, b = blockIdx.z;
    int lane = tid & 31, wid = tid >> 5;
    __shared__ float slS[MM][HD];
    __shared__ float bmaxS[MM];
    __shared__ float wsum[4][64];
    for (int i = tid; i < MM * (HD / 4); i += 128) {
        int m = i >> 4, d4 = i & 15;
        *(float4*)&slS[m][d4 * 4] = *(const float4*)&g_sl[m * DD + h * HD + d4 * 4];
    }
    if (tid < 64) bmaxS[tid] = g_bmax[tid];
    __syncthreads();
    ull ta[32], tb[32];
    {
        float rn0 = g_rn[b * SS + t0];
        const __half* xp = &g_xn[((size_t)(b * SS + t0)) * DD + h * HD];
#pragma unroll
        for (int i = 0; i < 8; i++) {
            float4 raw = *(const float4*)(xp + i * 8);
            const __half2* h2 = (const __half2*)&raw;
#pragma unroll
            for (int q = 0; q < 4; q++) {
                float2 f = __half22float2(h2[q]);
                ta[4 * i + q] = pk2(f.x * rn0, f.y * rn0);
            }
        }
        float rn1 = g_rn[b * SS + t0 + 128];
        const __half* xq = &g_xn[((size_t)(b * SS + t0 + 128)) * DD + h * HD];
#pragma unroll
        for (int i = 0; i < 8; i++) {
            float4 raw = *(const float4*)(xq + i * 8);
            const __half2* h2 = (const __half2*)&raw;
#pragma unroll
            for (int q = 0; q < 4; q++) {
                float2 f = __half22float2(h2[q]);
                tb[4 * i + q] = pk2(f.x * rn1, f.y * rn1);
            }
        }
    }
    float s0 = 0.f, s1 = 0.f;
    size_t lbase = (size_t)((b * HH + h) * MM) * SS;
    for (int m = 0; m < MM; m++) {
        ull a0 = 0, a1 = 0, c0 = 0, c1 = 0;
#pragma unroll
        for (int j = 0; j < 16; j++) {
            ulonglong2 sv = *(const ulonglong2*)&slS[m][j * 4];
            FMA2(a0, ta[2 * j], sv.x); FMA2(a1, ta[2 * j + 1], sv.y);
            FMA2(c0, tb[2 * j], sv.x); FMA2(c1, tb[2 * j + 1], sv.y);
        }
        float p0, p1, q0, q1, r0, r1, u0, u1;
        upk2(a0, p0, p1); upk2(a1, q0, q1);
        upk2(c0, r0, r1); upk2(c1, u0, u1);
        float bm = bmaxS[m];
        float e0 = __expf(((p0 + p1) + (q0 + q1)) - bm);
        float e1 = __expf(((r0 + r1) + (u0 + u1)) - bm);
        __half h0 = __float2half(e0);
        __half h1 = __float2half(e1);
        g_lh[lbase + (size_t)m * SS + t0]       = h0;
        g_lh[lbase + (size_t)m * SS + t0 + 128] = h1;
        float ws = __half2float(h0) + __half2float(h1);
#pragma unroll
        for (int o = 16; o; o >>= 1) ws += __shfl_xor_sync(~0u, ws, o);
        if (lane == (m & 31)) { if (m < 32) s0 = ws; else s1 = ws; }
    }
    wsum[wid][lane] = s0;
    wsum[wid][lane + 32] = s1;
    __syncthreads();
    if (tid < 64) {
        float tot = wsum[0][tid] + wsum[1][tid] + wsum[2][tid] + wsum[3][tid];
        atomicAdd(&g_rsum[(b * HH + h) * MM + tid], tot);
    }
}

// ---------------- K3: init -----------------------------------------------------
__global__ void k_binit(const float* __restrict__ b1, const float* __restrict__ b2) {
    int i = blockIdx.x * 256 + threadIdx.x;
    const int N1 = BB * MM * DD;
    const int N2 = BB * MM * FF;
    if (i < N1) g_y[i] = 0.f;
    else if (i < N1 + N2) { int k = i - N1; g_hid[k] = b1[k % (MM * FF)]; }
    else { int k = i - N1 - N2; g_y2[k] = b2[k % (MM * DD)]; }
}

// ---------------- K4: dispatch, 8m x 8d, no expf ---------------------------------
__global__ void __launch_bounds__(128) k_disp() {
    int ch = blockIdx.x, h = blockIdx.y, b = blockIdx.z;
    int tid = threadIdx.x;
    int sp = tid >> 6;
    int w  = tid & 63;
    int mg = w >> 3;   // 8 groups of 8 m
    int dg = w & 7;    // 8 groups of 8 d
    __shared__ float2 pT2[64][66];    // [s][m] dup pairs
    __shared__ float xts[64][72];     // [s][d]
    __shared__ float sinv[64];
    if (tid < 64) sinv[tid] = 1.f / g_rsum[(b * HH + h) * MM + tid];
    ull acc[8][4];
#pragma unroll
    for (int i = 0; i < 8; i++)
#pragma unroll
        for (int j = 0; j < 4; j++) acc[i][j] = 0ull;
    size_t lbh = (size_t)((b * HH + h) * MM) * SS;
    for (int tile = 0; tile < 8; tile++) {
        int s0 = (ch * 8 + tile) * 64;
        __syncthreads();
        for (int i = tid; i < 64 * 32; i += 128) {
            int m = i >> 5, s2 = i & 31;
            __half2 hv = *(const __half2*)&g_lh[lbh + (size_t)m * SS + s0 + 2 * s2];
            float2 f = __half22float2(hv);
            float minv = sinv[m];
            float e0 = f.x * minv, e1 = f.y * minv;
            pT2[2 * s2][m]     = make_float2(e0, e0);
            pT2[2 * s2 + 1][m] = make_float2(e1, e1);
        }
        for (int i = tid; i < 64 * 8; i += 128) {
            int s = i >> 3, c8 = i & 7;
            float4 raw = *(const float4*)&g_xn[((size_t)(b * SS + s0 + s)) * DD + h * HD + c8 * 8];
            const __half2* h2 = (const __half2*)&raw;
            float2 f0 = __half22float2(h2[0]), f1 = __half22float2(h2[1]);
            float2 f2 = __half22float2(h2[2]), f3 = __half22float2(h2[3]);
            *(float4*)&xts[s][c8 * 8]     = make_float4(f0.x, f0.y, f1.x, f1.y);
            *(float4*)&xts[s][c8 * 8 + 4] = make_float4(f2.x, f2.y, f3.x, f3.y);
        }
        __syncthreads();
#pragma unroll 2
        for (int s = sp; s < 64; s += 2) {
            ulonglong2 xa = *(const ulonglong2*)&xts[s][dg * 8];
            ulonglong2 xb = *(const ulonglong2*)&xts[s][dg * 8 + 4];
            ulonglong2 pa = *(const ulonglong2*)&pT2[s][mg * 8];
            ulonglong2 pb = *(const ulonglong2*)&pT2[s][mg * 8 + 2];
            ulonglong2 pc = *(const ulonglong2*)&pT2[s][mg * 8 + 4];
            ulonglong2 pd = *(const ulonglong2*)&pT2[s][mg * 8 + 6];
            FMA2(acc[0][0], pa.x, xa.x); FMA2(acc[0][1], pa.x, xa.y); FMA2(acc[0][2], pa.x, xb.x); FMA2(acc[0][3], pa.x, xb.y);
            FMA2(acc[1][0], pa.y, xa.x); FMA2(acc[1][1], pa.y, xa.y); FMA2(acc[1][2], pa.y, xb.x); FMA2(acc[1][3], pa.y, xb.y);
            FMA2(acc[2][0], pb.x, xa.x); FMA2(acc[2][1], pb.x, xa.y); FMA2(acc[2][2], pb.x, xb.x); FMA2(acc[2][3], pb.x, xb.y);
            FMA2(acc[3][0], pb.y, xa.x); FMA2(acc[3][1], pb.y, xa.y); FMA2(acc[3][2], pb.y, xb.x); FMA2(acc[3][3], pb.y, xb.y);
            FMA2(acc[4][0], pc.x, xa.x); FMA2(acc[4][1], pc.x, xa.y); FMA2(acc[4][2], pc.x, xb.x); FMA2(acc[4][3], pc.x, xb.y);
            FMA2(acc[5][0], pc.y, xa.x); FMA2(acc[5][1], pc.y, xa.y); FMA2(acc[5][2], pc.y, xb.x); FMA2(acc[5][3], pc.y, xb.y);
            FMA2(acc[6][0], pd.x, xa.x); FMA2(acc[6][1], pd.x, xa.y); FMA2(acc[6][2], pd.x, xb.x); FMA2(acc[6][3], pd.x, xb.y);
            FMA2(acc[7][0], pd.y, xa.x); FMA2(acc[7][1], pd.y, xa.y); FMA2(acc[7][2], pd.y, xb.x); FMA2(acc[7][3], pd.y, xb.y);
        }
    }
#pragma unroll
    for (int mi = 0; mi < 8; mi++) {
        int m = mg * 8 + mi;
        float* base = &g_y[((size_t)(b * MM + m)) * DD + h * HD + dg * 8];
#pragma unroll
        for (int j = 0; j < 4; j++) {
            float a0, a1;
            upk2(acc[mi][j], a0, a1);
            atomicAdd(base + 2 * j, a0);
            atomicAdd(base + 2 * j + 1, a1);
        }
    }
}

// ---------------- K5: fc1, kc=4, ldcs ---------------------------------------------
__global__ void __launch_bounds__(256) k_fc1(const float* __restrict__ w1) {
    int fblk = blockIdx.x, m = blockIdx.y, kc = blockIdx.z;
    int tid = threadIdx.x;
    int f = fblk * 1024 + tid * 4;
    __shared__ float ysT[192][12];
    for (int i = tid; i < 8 * 192; i += 256) {
        int bb = i / 192, k = i % 192;
        ysT[k][bb] = g_y[((size_t)(bb * MM + m)) * DD + kc * 192 + k];
    }
    __syncthreads();
    ull acc[4][4];
#pragma unroll
    for (int i = 0; i < 4; i++)
#pragma unroll
        for (int j = 0; j < 4; j++) acc[i][j] = 0ull;
    const float* wp = w1 + (size_t)m * DD * FF + (size_t)(kc * 192) * FF + f;
#pragma unroll 8
    for (int k = 0; k < 192; k++) {
        float4 wv = __ldcs((const float4*)(wp + (size_t)k * FF));
        ulonglong2 ya = *(const ulonglong2*)&ysT[k][0];
        ulonglong2 yb = *(const ulonglong2*)&ysT[k][4];
        ull w0 = pk2(wv.x, wv.x), w1d = pk2(wv.y, wv.y);
        ull w2 = pk2(wv.z, wv.z), w3 = pk2(wv.w, wv.w);
        FMA2(acc[0][0], w0, ya.x); FMA2(acc[0][1], w0, ya.y); FMA2(acc[0][2], w0, yb.x); FMA2(acc[0][3], w0, yb.y);
        FMA2(acc[1][0], w1d, ya.x); FMA2(acc[1][1], w1d, ya.y); FMA2(acc[1][2], w1d, yb.x); FMA2(acc[1][3], w1d, yb.y);
        FMA2(acc[2][0], w2, ya.x); FMA2(acc[2][1], w2, ya.y); FMA2(acc[2][2], w2, yb.x); FMA2(acc[2][3], w2, yb.y);
        FMA2(acc[3][0], w3, ya.x); FMA2(acc[3][1], w3, ya.y); FMA2(acc[3][2], w3, yb.x); FMA2(acc[3][3], w3, yb.y);
    }
#pragma unroll
    for (int fi = 0; fi < 4; fi++)
#pragma unroll
        for (int bp = 0; bp < 4; bp++) {
            float a0, a1;
            upk2(acc[fi][bp], a0, a1);
            atomicAdd(&g_hid[((size_t)((2 * bp) * MM + m)) * FF + f + fi], a0);
            atomicAdd(&g_hid[((size_t)((2 * bp + 1) * MM + m)) * FF + f + fi], a1);
        }
}

// ---------------- K6: fc2 (gelu on load), kc=12, ldcs ------------------------------
__global__ void __launch_bounds__(192) k_fc2(const float* __restrict__ w2) {
    int m = blockIdx.x, kc = blockIdx.y;
    int tid = threadIdx.x;
    int d = tid * 4;
    __shared__ float hsT[256][12];
    for (int i = tid; i < 8 * 256; i += 192) {
        int bb = i >> 8, k = i & 255;
        float v = g_hid[((size_t)(bb * MM + m)) * FF + kc * 256 + k];
        hsT[k][bb] = 0.5f * v * (1.f + erff(v * 0.70710678118654752f));
    }
    __syncthreads();
    ull acc[4][4];
#pragma unroll
    for (int i = 0; i < 4; i++)
#pragma unroll
        for (int j = 0; j < 4; j++) acc[i][j] = 0ull;
    const float* wp = w2 + (size_t)m * FF * DD + (size_t)(kc * 256) * DD + d;
#pragma unroll 8
    for (int k = 0; k < 256; k++) {
        float4 wv = __ldcs((const float4*)(wp + (size_t)k * DD));
        ulonglong2 ya = *(const ulonglong2*)&hsT[k][0];
        ulonglong2 yb = *(const ulonglong2*)&hsT[k][4];
        ull w0 = pk2(wv.x, wv.x), w1d = pk2(wv.y, wv.y);
        ull w2d = pk2(wv.z, wv.z), w3 = pk2(wv.w, wv.w);
        FMA2(acc[0][0], w0, ya.x); FMA2(acc[0][1], w0, ya.y); FMA2(acc[0][2], w0, yb.x); FMA2(acc[0][3], w0, yb.y);
        FMA2(acc[1][0], w1d, ya.x); FMA2(acc[1][1], w1d, ya.y); FMA2(acc[1][2], w1d, yb.x); FMA2(acc[1][3], w1d, yb.y);
        FMA2(acc[2][0], w2d, ya.x); FMA2(acc[2][1], w2d, ya.y); FMA2(acc[2][2], w2d, yb.x); FMA2(acc[2][3], w2d, yb.y);
        FMA2(acc[3][0], w3, ya.x); FMA2(acc[3][1], w3, ya.y); FMA2(acc[3][2], w3, yb.x); FMA2(acc[3][3], w3, yb.y);
    }
#pragma unroll
    for (int di = 0; di < 4; di++)
#pragma unroll
        for (int bp = 0; bp < 4; bp++) {
            float a0, a1;
            upk2(acc[di][bp], a0, a1);
            atomicAdd(&g_y2[((size_t)((2 * bp) * MM + m)) * DD + d + di], a0);
            atomicAdd(&g_y2[((size_t)((2 * bp + 1) * MM + m)) * DD + d + di], a1);
        }
}

// ---------------- K7: combine, no max pass -----------------------------------------
__global__ void __launch_bounds__(128) k_comb(float* __restrict__ out) {
    int sb = blockIdx.x, h = blockIdx.y, b = blockIdx.z;
    int s0 = sb * 64;
    int tid = threadIdx.x;
    __shared__ float2 pDup[64][66];   // [m][s] dup pairs of p = E * c_m
    __shared__ float y2s[64][72];
    __shared__ float psum[2][64], sinvs[64], cs[64];
    if (tid < 64) cs[tid] = g_cm[tid];
    __syncthreads();
    size_t lbh = (size_t)((b * HH + h) * MM) * SS;
    for (int i = tid; i < 64 * 32; i += 128) {
        int m = i >> 5, s2 = i & 31;
        __half2 hv = *(const __half2*)&g_lh[lbh + (size_t)m * SS + s0 + 2 * s2];
        float2 f = __half22float2(hv);
        float c = cs[m];
        float4 dup = make_float4(f.x * c, f.x * c, f.y * c, f.y * c);
        *(float4*)&pDup[m][2 * s2] = dup;
    }
    for (int i = tid; i < 64 * 16; i += 128) {
        int m = i >> 4, d4 = i & 15;
        *(float4*)&y2s[m][d4 * 4] =
            *(const float4*)&g_y2[((size_t)(b * MM + m)) * DD + h * HD + d4 * 4];
    }
    __syncthreads();
    {
        int t = tid & 63, mh = tid >> 6;
        float sm = 0.f;
#pragma unroll 8
        for (int mm = 0; mm < 32; mm++) sm += pDup[mh * 32 + mm][t].x;
        psum[mh][t] = sm;
    }
    __syncthreads();
    if (tid < 64) sinvs[tid] = 1.f / (psum[0][tid] + psum[1][tid]);
    __syncthreads();
    int sg = tid >> 3, dgrp = tid & 7;
    ull acc[4][4];
#pragma unroll
    for (int i = 0; i < 4; i++)
#pragma unroll
        for (int j = 0; j < 4; j++) acc[i][j] = 0ull;
#pragma unroll 4
    for (int m = 0; m < 64; m++) {
        ulonglong2 pa = *(const ulonglong2*)&pDup[m][sg * 4];
        ulonglong2 pb = *(const ulonglong2*)&pDup[m][sg * 4 + 2];
        ulonglong2 ya = *(const ulonglong2*)&y2s[m][dgrp * 8];
        ulonglong2 yb = *(const ulonglong2*)&y2s[m][dgrp * 8 + 4];
        FMA2(acc[0][0], pa.x, ya.x); FMA2(acc[0][1], pa.x, ya.y); FMA2(acc[0][2], pa.x, yb.x); FMA2(acc[0][3], pa.x, yb.y);
        FMA2(acc[1][0], pa.y, ya.x); FMA2(acc[1][1], pa.y, ya.y); FMA2(acc[1][2], pa.y, yb.x); FMA2(acc[1][3], pa.y, yb.y);
        FMA2(acc[2][0], pb.x, ya.x); FMA2(acc[2][1], pb.x, ya.y); FMA2(acc[2][2], pb.x, yb.x); FMA2(acc[2][3], pb.x, yb.y);
        FMA2(acc[3][0], pb.y, ya.x); FMA2(acc[3][1], pb.y, ya.y); FMA2(acc[3][2], pb.y, yb.x); FMA2(acc[3][3], pb.y, yb.y);
    }
#pragma unroll
    for (int ss = 0; ss < 4; ss++) {
        int s = s0 + sg * 4 + ss;
        float inv = sinvs[sg * 4 + ss];
        float o0, o1, o2, o3, o4, o5, o6, o7;
        upk2(acc[ss][0], o0, o1); upk2(acc[ss][1], o2, o3);
        upk2(acc[ss][2], o4, o5); upk2(acc[ss][3], o6, o7);
        float* op = &out[((size_t)(b * SS + s)) * DD + h * HD + dgrp * 8];
        *(float4*)(op + 0) = make_float4(o0 * inv, o1 * inv, o2 * inv, o3 * inv);
        *(float4*)(op + 4) = make_float4(o4 * inv, o5 * inv, o6 * inv, o7 * inv);
    }
}

// ---------------- launch --------------------------------------------------------
extern "C" void kernel_launch(void* const* d_in, const int* in_sizes, int n_in,
                              void* d_out, int out_size) {
    const float* x      = (const float*)d_in[0];
    const float* slots  = (const float*)d_in[1];
    const float* scale  = (const float*)d_in[2];
    const float* fc1_w  = (const float*)d_in[3];
    const float* fc1_b  = (const float*)d_in[4];
    const float* fc2_w  = (const float*)d_in[5];
    const float* fc2_b  = (const float*)d_in[6];
    const float* norm_w = (const float*)d_in[7];
    float* out = (float*)d_out;

    k_slots<<<MM, 256>>>(slots, scale);
    k_norm<<<BB * SS / 8, 256>>>(x, norm_w);
    k_logits<<<dim3(SS / 256, HH, BB), 128>>>();
    k_binit<<<(BB * MM * (2 * DD + FF)) / 256, 256>>>(fc1_b, fc2_b);
    k_disp<<<dim3(8, HH, BB), 128>>>();
    k_fc1<<<dim3(3, MM, 4), 256>>>(fc1_w);
    k_fc2<<<dim3(MM, 12), 192>>>(fc2_w);
    k_comb<<<dim3(SS / 64, HH, BB), 128>>>(out);
}

// round 6
// speedup vs baseline: 1.1020x; 1.1020x over previous
#include <cuda_runtime.h>
#include <cuda_fp16.h>
#include <math.h>

#define BB 8
#define SS 4096
#define DD 768
#define MM 64
#define FF 3072
#define HH 12
#define HD 64
#define EPSF 1e-5f

typedef unsigned long long ull;

__device__ __forceinline__ ull pk2(float lo, float hi) {
    ull r;
    asm("mov.b64 %0, {%1, %2};" : "=l"(r) : "f"(lo), "f"(hi));
    return r;
}
__device__ __forceinline__ void upk2(ull v, float& lo, float& hi) {
    asm("mov.b64 {%0, %1}, %2;" : "=f"(lo), "=f"(hi) : "l"(v));
}
#define FMA2(a, x, y) asm("fma.rn.f32x2 %0, %1, %2, %0;" : "+l"(a) : "l"(x), "l"(y))

// ---------------- scratch -----------------------------------------------------
__device__ float  g_sl[MM * DD];
__device__ float  g_xn[BB * SS * DD];
__device__ float  g_rn[BB * SS];
__device__ __half g_lh[(size_t)BB * HH * MM * SS];
__device__ float  g_rmax[BB * HH * MM];
__device__ float  g_rsum[BB * HH * MM];
__device__ float  g_y[BB * MM * DD];
__device__ float  g_hid[(size_t)BB * MM * FF];
__device__ float  g_y2[BB * MM * DD];

// ---------------- K0: slots ---------------------------------------------------
__global__ void k_slots(const float* __restrict__ slots, const float* __restrict__ scale) {
    int m = blockIdx.x, tid = threadIdx.x;
    __shared__ float red[8];
    float ss = 0.f;
    for (int i = tid; i < DD; i += 256) { float v = slots[m * DD + i]; ss += v * v; }
    for (int o = 16; o; o >>= 1) ss += __shfl_down_sync(~0u, ss, o);
    if ((tid & 31) == 0) red[tid >> 5] = ss;
    __syncthreads();
    if (tid == 0) { float s = 0; for (int i = 0; i < 8; i++) s += red[i]; red[0] = s; }
    __syncthreads();
    float inv = scale[m] / fmaxf(sqrtf(red[0]), EPSF);
    for (int i = tid; i < DD; i += 256) g_sl[m * DD + i] = slots[m * DD + i] * inv;
}

// ---------------- K1: rmsnorm + token l2 inv-norm ------------------------------
__global__ void k_norm(const float* __restrict__ x, const float* __restrict__ nw) {
    int t = blockIdx.x, tid = threadIdx.x;
    __shared__ float red[6];
    __shared__ float bval;
    float4 v = ((const float4*)(x + (size_t)t * DD))[tid];
    float ss = v.x * v.x + v.y * v.y + v.z * v.z + v.w * v.w;
    for (int o = 16; o; o >>= 1) ss += __shfl_down_sync(~0u, ss, o);
    if ((tid & 31) == 0) red[tid >> 5] = ss;
    __syncthreads();
    if (tid == 0) {
        float s = 0; for (int i = 0; i < 6; i++) s += red[i];
        bval = rsqrtf(s / (float)DD + EPSF);
    }
    __syncthreads();
    float rstd = bval;
    float4 w = ((const float4*)nw)[tid];
    float4 a;
    a.x = v.x * rstd * w.x; a.y = v.y * rstd * w.y;
    a.z = v.z * rstd * w.z; a.w = v.w * rstd * w.w;
    ((float4*)(g_xn + (size_t)t * DD))[tid] = a;
    float s2 = a.x * a.x + a.y * a.y + a.z * a.z + a.w * a.w;
    for (int o = 16; o; o >>= 1) s2 += __shfl_down_sync(~0u, s2, o);
    __syncthreads();
    if ((tid & 31) == 0) red[tid >> 5] = s2;
    __syncthreads();
    if (tid == 0) {
        float s = 0; for (int i = 0; i < 6; i++) s += red[i];
        g_rn[t] = 1.f / fmaxf(sqrtf(s), EPSF);
    }
}

// ---------------- K2: binit ------------------------------------------------------
__global__ void k_binit(const float* __restrict__ b1, const float* __restrict__ b2) {
    int i = blockIdx.x * 256 + threadIdx.x;
    const int N1 = BB * MM * DD;
    const int N2 = BB * MM * FF;
    if (i < N1) g_y[i] = 0.f;
    else if (i < N1 + N2) { int k = i - N1; g_hid[k] = b1[k % (MM * FF)]; }
    else { int k = i - N1 - N2; g_y2[k] = b2[k % (MM * DD)]; }
}

// ---------------- K3: logits (profiled at launch index 3) ------------------------
__global__ void __launch_bounds__(128) k_logits() {
    int t0 = blockIdx.x * 256 + threadIdx.x;
    int h = blockIdx.y, b = blockIdx.z;
    __shared__ float slS[MM][HD];
    for (int i = threadIdx.x; i < MM * (HD / 4); i += 128) {
        int m = i >> 4, d4 = i & 15;
        *(float4*)&slS[m][d4 * 4] = *(const float4*)&g_sl[m * DD + h * HD + d4 * 4];
    }
    __syncthreads();
    ull ta[32], tb[32];
    {
        float rn0 = g_rn[b * SS + t0];
        const float* xp = &g_xn[((size_t)(b * SS + t0)) * DD + h * HD];
#pragma unroll
        for (int i = 0; i < 16; i++) {
            float4 v = *(const float4*)(xp + i * 4);
            ta[2 * i] = pk2(v.x * rn0, v.y * rn0);
            ta[2 * i + 1] = pk2(v.z * rn0, v.w * rn0);
        }
        float rn1 = g_rn[b * SS + t0 + 128];
        const float* xq = &g_xn[((size_t)(b * SS + t0 + 128)) * DD + h * HD];
#pragma unroll
        for (int i = 0; i < 16; i++) {
            float4 v = *(const float4*)(xq + i * 4);
            tb[2 * i] = pk2(v.x * rn1, v.y * rn1);
            tb[2 * i + 1] = pk2(v.z * rn1, v.w * rn1);
        }
    }
    size_t lbase = (size_t)((b * HH + h) * MM) * SS;
    for (int m = 0; m < MM; m++) {
        ull a0 = 0, a1 = 0, c0 = 0, c1 = 0;
#pragma unroll
        for (int j = 0; j < 16; j++) {
            ulonglong2 sv = *(const ulonglong2*)&slS[m][j * 4];
            FMA2(a0, ta[2 * j], sv.x); FMA2(a1, ta[2 * j + 1], sv.y);
            FMA2(c0, tb[2 * j], sv.x); FMA2(c1, tb[2 * j + 1], sv.y);
        }
        float p0, p1, q0, q1, r0, r1, u0, u1;
        upk2(a0, p0, p1); upk2(a1, q0, q1);
        upk2(c0, r0, r1); upk2(c1, u0, u1);
        g_lh[lbase + (size_t)m * SS + t0]       = __float2half((p0 + p1) + (q0 + q1));
        g_lh[lbase + (size_t)m * SS + t0 + 128] = __float2half((r0 + r1) + (u0 + u1));
    }
}

// ---------------- K4: one-pass softmax stats -----------------------------------
__global__ void __launch_bounds__(128) k_stats() {
    int r = blockIdx.x, tid = threadIdx.x;
    const __half* row = g_lh + (size_t)r * SS;
    float4 raw[4];
    const float4* p = (const float4*)(row + tid * 32);
#pragma unroll
    for (int q = 0; q < 4; q++) raw[q] = p[q];
    float v[32];
#pragma unroll
    for (int q = 0; q < 4; q++) {
        const __half2* h2 = (const __half2*)&raw[q];
#pragma unroll
        for (int j = 0; j < 4; j++) {
            float2 f = __half22float2(h2[j]);
            v[q * 8 + j * 2] = f.x; v[q * 8 + j * 2 + 1] = f.y;
        }
    }
    float mx = -1e30f;
#pragma unroll
    for (int i = 0; i < 32; i++) mx = fmaxf(mx, v[i]);
    __shared__ float red[4];
    __shared__ float smxv;
    for (int o = 16; o; o >>= 1) mx = fmaxf(mx, __shfl_down_sync(~0u, mx, o));
    if ((tid & 31) == 0) red[tid >> 5] = mx;
    __syncthreads();
    if (tid == 0) smxv = fmaxf(fmaxf(red[0], red[1]), fmaxf(red[2], red[3]));
    __syncthreads();
    float gmx = smxv;
    float sm = 0.f;
#pragma unroll
    for (int i = 0; i < 32; i++) sm += __expf(v[i] - gmx);
    for (int o = 16; o; o >>= 1) sm += __shfl_down_sync(~0u, sm, o);
    __syncthreads();
    if ((tid & 31) == 0) red[tid >> 5] = sm;
    __syncthreads();
    if (tid == 0) {
        g_rmax[r] = gmx;
        g_rsum[r] = red[0] + red[1] + red[2] + red[3];
    }
}

// ---------------- K5: dispatch (round-2 proven version) ---------------------------
__global__ void __launch_bounds__(128) k_disp() {
    int ch = blockIdx.x, h = blockIdx.y, b = blockIdx.z;
    int tid = threadIdx.x;
    int sp = tid >> 6;
    int w  = tid & 63;
    int mg = w >> 4;
    int dg = w & 15;
    __shared__ float pT[64][68];
    __shared__ float xts[64][68];
    __shared__ float smax[64], sinv[64];
    if (tid < 64) {
        int r = (b * HH + h) * MM + tid;
        smax[tid] = g_rmax[r];
        sinv[tid] = 1.f / g_rsum[r];
    }
    ull accL[16], accH[16];
#pragma unroll
    for (int j = 0; j < 16; j++) { accL[j] = 0ull; accH[j] = 0ull; }
    size_t lbh = (size_t)((b * HH + h) * MM) * SS;
    for (int tile = 0; tile < 8; tile++) {
        int s0 = (ch * 8 + tile) * 64;
        __syncthreads();
        for (int i = tid; i < 64 * 32; i += 128) {
            int m = i >> 5, s2 = i & 31;
            __half2 hv = *(const __half2*)&g_lh[lbh + (size_t)m * SS + s0 + 2 * s2];
            float2 f = __half22float2(hv);
            float mmax = smax[m], minv = sinv[m];
            pT[2 * s2][m]     = __expf(f.x - mmax) * minv;
            pT[2 * s2 + 1][m] = __expf(f.y - mmax) * minv;
        }
        for (int i = tid; i < 64 * 16; i += 128) {
            int s = i >> 4, d4 = i & 15;
            *(float4*)&xts[s][d4 * 4] =
                *(const float4*)&g_xn[((size_t)(b * SS + s0 + s)) * DD + h * HD + d4 * 4];
        }
        __syncthreads();
#pragma unroll 2
        for (int s = sp; s < 64; s += 2) {
            float4 xv = *(const float4*)&xts[s][dg * 4];
            ull xlo = pk2(xv.x, xv.y), xhi = pk2(xv.z, xv.w);
#pragma unroll
            for (int j = 0; j < 4; j++) {
                float4 pv = *(const float4*)&pT[s][mg * 16 + j * 4];
                ull p0 = pk2(pv.x, pv.x), p1 = pk2(pv.y, pv.y);
                ull p2 = pk2(pv.z, pv.z), p3 = pk2(pv.w, pv.w);
                FMA2(accL[j * 4 + 0], p0, xlo); FMA2(accH[j * 4 + 0], p0, xhi);
                FMA2(accL[j * 4 + 1], p1, xlo); FMA2(accH[j * 4 + 1], p1, xhi);
                FMA2(accL[j * 4 + 2], p2, xlo); FMA2(accH[j * 4 + 2], p2, xhi);
                FMA2(accL[j * 4 + 3], p3, xlo); FMA2(accH[j * 4 + 3], p3, xhi);
            }
        }
    }
#pragma unroll
    for (int ml = 0; ml < 16; ml++) {
        int m = mg * 16 + ml;
        float a0, a1, a2, a3;
        upk2(accL[ml], a0, a1); upk2(accH[ml], a2, a3);
        float* base = &g_y[((size_t)(b * MM + m)) * DD + h * HD + dg * 4];
        atomicAdd(base + 0, a0);
        atomicAdd(base + 1, a1);
        atomicAdd(base + 2, a2);
        atomicAdd(base + 3, a3);
    }
}

// ---------------- K6: fc1, batch-pair + prefetch ----------------------------------
__global__ void __launch_bounds__(256) k_fc1(const float* __restrict__ w1) {
    int fblk = blockIdx.x, m = blockIdx.y, kc = blockIdx.z;
    int tid = threadIdx.x;
    int f = fblk * 1024 + tid * 4;
    __shared__ float ysT[192][12];
    for (int i = tid; i < 8 * 192; i += 256) {
        int bb = i / 192, k = i % 192;
        ysT[k][bb] = g_y[((size_t)(bb * MM + m)) * DD + kc * 192 + k];
    }
    __syncthreads();
    ull acc[4][4];
#pragma unroll
    for (int i = 0; i < 4; i++)
#pragma unroll
        for (int j = 0; j < 4; j++) acc[i][j] = 0ull;
    const float* wp = w1 + (size_t)m * DD * FF + (size_t)(kc * 192) * FF + f;
    float4 wv = *(const float4*)wp;
#pragma unroll 4
    for (int k = 0; k < 192; k++) {
        float4 wn;
        if (k < 191) wn = *(const float4*)(wp + (size_t)(k + 1) * FF);
        ulonglong2 ya = *(const ulonglong2*)&ysT[k][0];
        ulonglong2 yb = *(const ulonglong2*)&ysT[k][4];
        ull w0 = pk2(wv.x, wv.x), w1d = pk2(wv.y, wv.y);
        ull w2 = pk2(wv.z, wv.z), w3 = pk2(wv.w, wv.w);
        FMA2(acc[0][0], w0, ya.x); FMA2(acc[0][1], w0, ya.y); FMA2(acc[0][2], w0, yb.x); FMA2(acc[0][3], w0, yb.y);
        FMA2(acc[1][0], w1d, ya.x); FMA2(acc[1][1], w1d, ya.y); FMA2(acc[1][2], w1d, yb.x); FMA2(acc[1][3], w1d, yb.y);
        FMA2(acc[2][0], w2, ya.x); FMA2(acc[2][1], w2, ya.y); FMA2(acc[2][2], w2, yb.x); FMA2(acc[2][3], w2, yb.y);
        FMA2(acc[3][0], w3, ya.x); FMA2(acc[3][1], w3, ya.y); FMA2(acc[3][2], w3, yb.x); FMA2(acc[3][3], w3, yb.y);
        wv = wn;
    }
#pragma unroll
    for (int fi = 0; fi < 4; fi++)
#pragma unroll
        for (int bp = 0; bp < 4; bp++) {
            float a0, a1;
            upk2(acc[fi][bp], a0, a1);
            atomicAdd(&g_hid[((size_t)((2 * bp) * MM + m)) * FF + f + fi], a0);
            atomicAdd(&g_hid[((size_t)((2 * bp + 1) * MM + m)) * FF + f + fi], a1);
        }
}

// ---------------- K7: fc2 (gelu on load), batch-pair + prefetch --------------------
__global__ void __launch_bounds__(192) k_fc2(const float* __restrict__ w2) {
    int m = blockIdx.x, kc = blockIdx.y;
    int tid = threadIdx.x;
    int d = tid * 4;
    __shared__ float hsT[384][12];
    for (int i = tid; i < 8 * 384; i += 192) {
        int bb = i / 384, k = i % 384;
        float v = g_hid[((size_t)(bb * MM + m)) * FF + kc * 384 + k];
        hsT[k][bb] = 0.5f * v * (1.f + erff(v * 0.70710678118654752f));
    }
    __syncthreads();
    ull acc[4][4];
#pragma unroll
    for (int i = 0; i < 4; i++)
#pragma unroll
        for (int j = 0; j < 4; j++) acc[i][j] = 0ull;
    const float* wp = w2 + (size_t)m * FF * DD + (size_t)(kc * 384) * DD + d;
    float4 wv = *(const float4*)wp;
#pragma unroll 4
    for (int k = 0; k < 384; k++) {
        float4 wn;
        if (k < 383) wn = *(const float4*)(wp + (size_t)(k + 1) * DD);
        ulonglong2 ya = *(const ulonglong2*)&hsT[k][0];
        ulonglong2 yb = *(const ulonglong2*)&hsT[k][4];
        ull w0 = pk2(wv.x, wv.x), w1d = pk2(wv.y, wv.y);
        ull w2d = pk2(wv.z, wv.z), w3 = pk2(wv.w, wv.w);
        FMA2(acc[0][0], w0, ya.x); FMA2(acc[0][1], w0, ya.y); FMA2(acc[0][2], w0, yb.x); FMA2(acc[0][3], w0, yb.y);
        FMA2(acc[1][0], w1d, ya.x); FMA2(acc[1][1], w1d, ya.y); FMA2(acc[1][2], w1d, yb.x); FMA2(acc[1][3], w1d, yb.y);
        FMA2(acc[2][0], w2d, ya.x); FMA2(acc[2][1], w2d, ya.y); FMA2(acc[2][2], w2d, yb.x); FMA2(acc[2][3], w2d, yb.y);
        FMA2(acc[3][0], w3, ya.x); FMA2(acc[3][1], w3, ya.y); FMA2(acc[3][2], w3, yb.x); FMA2(acc[3][3], w3, yb.y);
        wv = wn;
    }
#pragma unroll
    for (int di = 0; di < 4; di++)
#pragma unroll
        for (int bp = 0; bp < 4; bp++) {
            float a0, a1;
            upk2(acc[di][bp], a0, a1);
            atomicAdd(&g_y2[((size_t)((2 * bp) * MM + m)) * DD + d + di], a0);
            atomicAdd(&g_y2[((size_t)((2 * bp + 1) * MM + m)) * DD + d + di], a1);
        }
}

// ---------------- K8: combine (round-2 proven version) -----------------------------
__global__ void __launch_bounds__(128) k_comb(float* __restrict__ out) {
    int sb = blockIdx.x, h = blockIdx.y, b = blockIdx.z;
    int s0 = sb * 64;
    int tid = threadIdx.x;
    __shared__ float pSm[64][68];
    __shared__ float y2s[64][72];
    __shared__ float pmax[2][64], psum[2][64], smx[64], sinvs[64];
    size_t lbh = (size_t)((b * HH + h) * MM) * SS;
    for (int i = tid; i < 64 * 32; i += 128) {
        int m = i >> 5, s2 = i & 31;
        __half2 hv = *(const __half2*)&g_lh[lbh + (size_t)m * SS + s0 + 2 * s2];
        float2 f = __half22float2(hv);
        pSm[m][2 * s2] = f.x; pSm[m][2 * s2 + 1] = f.y;
    }
    for (int i = tid; i < 64 * 16; i += 128) {
        int m = i >> 4, d4 = i & 15;
        *(float4*)&y2s[m][d4 * 4] =
            *(const float4*)&g_y2[((size_t)(b * MM + m)) * DD + h * HD + d4 * 4];
    }
    __syncthreads();
    {
        int t = tid & 63, mh = tid >> 6;
        float mx = -1e30f;
#pragma unroll 8
        for (int mm = 0; mm < 32; mm++) mx = fmaxf(mx, pSm[mh * 32 + mm][t]);
        pmax[mh][t] = mx;
    }
    __syncthreads();
    if (tid < 64) smx[tid] = fmaxf(pmax[0][tid], pmax[1][tid]);
    __syncthreads();
    {
        int t = tid & 63, mh = tid >> 6;
        float mx = smx[t], sm = 0.f;
#pragma unroll 8
        for (int mm = 0; mm < 32; mm++) {
            float e = __expf(pSm[mh * 32 + mm][t] - mx);
            pSm[mh * 32 + mm][t] = e;
            sm += e;
        }
        psum[mh][t] = sm;
    }
    __syncthreads();
    if (tid < 64) sinvs[tid] = 1.f / (psum[0][tid] + psum[1][tid]);
    __syncthreads();
    int sg = tid >> 3, dgrp = tid & 7;
    ull acc[4][4];
#pragma unroll
    for (int i = 0; i < 4; i++)
#pragma unroll
        for (int j = 0; j < 4; j++) acc[i][j] = 0ull;
#pragma unroll 4
    for (int m = 0; m < 64; m++) {
        float4 pa = *(const float4*)&pSm[m][sg * 4];
        ull pd0 = pk2(pa.x, pa.x), pd1 = pk2(pa.y, pa.y);
        ull pd2 = pk2(pa.z, pa.z), pd3 = pk2(pa.w, pa.w);
        ulonglong2 yva = *(const ulonglong2*)&y2s[m][dgrp * 8];
        ulonglong2 yvb = *(const ulonglong2*)&y2s[m][dgrp * 8 + 4];
        FMA2(acc[0][0], pd0, yva.x); FMA2(acc[0][1], pd0, yva.y); FMA2(acc[0][2], pd0, yvb.x); FMA2(acc[0][3], pd0, yvb.y);
        FMA2(acc[1][0], pd1, yva.x); FMA2(acc[1][1], pd1, yva.y); FMA2(acc[1][2], pd1, yvb.x); FMA2(acc[1][3], pd1, yvb.y);
        FMA2(acc[2][0], pd2, yva.x); FMA2(acc[2][1], pd2, yva.y); FMA2(acc[2][2], pd2, yvb.x); FMA2(acc[2][3], pd2, yvb.y);
        FMA2(acc[3][0], pd3, yva.x); FMA2(acc[3][1], pd3, yva.y); FMA2(acc[3][2], pd3, yvb.x); FMA2(acc[3][3], pd3, yvb.y);
    }
#pragma unroll
    for (int ss = 0; ss < 4; ss++) {
        int s = s0 + sg * 4 + ss;
        float inv = sinvs[sg * 4 + ss];
        float o0, o1, o2, o3, o4, o5, o6, o7;
        upk2(acc[ss][0], o0, o1); upk2(acc[ss][1], o2, o3);
        upk2(acc[ss][2], o4, o5); upk2(acc[ss][3], o6, o7);
        float* op = &out[((size_t)(b * SS + s)) * DD + h * HD + dgrp * 8];
        *(float4*)(op + 0) = make_float4(o0 * inv, o1 * inv, o2 * inv, o3 * inv);
        *(float4*)(op + 4) = make_float4(o4 * inv, o5 * inv, o6 * inv, o7 * inv);
    }
}

// ---------------- launch --------------------------------------------------------
extern "C" void kernel_launch(void* const* d_in, const int* in_sizes, int n_in,
                              void* d_out, int out_size) {
    const float* x      = (const float*)d_in[0];
    const float* slots  = (const float*)d_in[1];
    const float* scale  = (const float*)d_in[2];
    const float* fc1_w  = (const float*)d_in[3];
    const float* fc1_b  = (const float*)d_in[4];
    const float* fc2_w  = (const float*)d_in[5];
    const float* fc2_b  = (const float*)d_in[6];
    const float* norm_w = (const float*)d_in[7];
    float* out = (float*)d_out;

    k_slots<<<MM, 256>>>(slots, scale);                                   // idx 0
    k_norm<<<BB * SS, 192>>>(x, norm_w);                                  // idx 1
    k_binit<<<(BB * MM * (2 * DD + FF)) / 256, 256>>>(fc1_b, fc2_b);      // idx 2
    k_logits<<<dim3(SS / 256, HH, BB), 128>>>();                          // idx 3 (profiled)
    k_stats<<<BB * HH * MM, 128>>>();                                     // idx 4
    k_disp<<<dim3(8, HH, BB), 128>>>();                                   // idx 5
    k_fc1<<<dim3(3, MM, 4), 256>>>(fc1_w);                                // idx 6
    k_fc2<<<dim3(MM, 8), 192>>>(fc2_w);                                   // idx 7
    k_comb<<<dim3(SS / 64, HH, BB), 128>>>(out);                          // idx 8
}

// round 7
// speedup vs baseline: 1.1980x; 1.0872x over previous
#include <cuda_runtime.h>
#include <cuda_fp16.h>
#include <math.h>

#define BB 8
#define SS 4096
#define DD 768
#define MM 64
#define FF 3072
#define HH 12
#define HD 64
#define EPSF 1e-5f

typedef unsigned long long ull;

__device__ __forceinline__ ull pk2(float lo, float hi) {
    ull r;
    asm("mov.b64 %0, {%1, %2};" : "=l"(r) : "f"(lo), "f"(hi));
    return r;
}
__device__ __forceinline__ void upk2(ull v, float& lo, float& hi) {
    asm("mov.b64 {%0, %1}, %2;" : "=f"(lo), "=f"(hi) : "l"(v));
}
#define FMA2(a, x, y) asm("fma.rn.f32x2 %0, %1, %2, %0;" : "+l"(a) : "l"(x), "l"(y))

__device__ __forceinline__ unsigned su32(const void* p) {
    return (unsigned)__cvta_generic_to_shared(p);
}

// ---------------- scratch -----------------------------------------------------
__device__ __half g_slh[MM * DD];               // l2norm(slots)*scale, fp16
__device__ float  g_xn[BB * SS * DD];           // rms-normed x, fp32
__device__ __half g_nh[BB * SS * DD];           // l2-normalized tokens, fp16
__device__ __half g_lh[(size_t)BB * HH * MM * SS];
__device__ float  g_rmax[BB * HH * MM];
__device__ float  g_rsum[BB * HH * MM];
__device__ float  g_y[BB * MM * DD];
__device__ float  g_hid[(size_t)BB * MM * FF];
__device__ float  g_y2[BB * MM * DD];

// ---------------- K0: slots (fp16 out) ------------------------------------------
__global__ void k_slots(const float* __restrict__ slots, const float* __restrict__ scale) {
    int m = blockIdx.x, tid = threadIdx.x;
    __shared__ float red[8];
    float ss = 0.f;
    for (int i = tid; i < DD; i += 256) { float v = slots[m * DD + i]; ss += v * v; }
    for (int o = 16; o; o >>= 1) ss += __shfl_down_sync(~0u, ss, o);
    if ((tid & 31) == 0) red[tid >> 5] = ss;
    __syncthreads();
    if (tid == 0) { float s = 0; for (int i = 0; i < 8; i++) s += red[i]; red[0] = s; }
    __syncthreads();
    float inv = scale[m] / fmaxf(sqrtf(red[0]), EPSF);
    for (int i = tid; i < DD; i += 256) g_slh[m * DD + i] = __float2half(slots[m * DD + i] * inv);
}

// ---------------- K1: rmsnorm -> g_xn fp32, normalized token -> g_nh fp16 --------
__global__ void k_norm(const float* __restrict__ x, const float* __restrict__ nw) {
    int t = blockIdx.x, tid = threadIdx.x;
    __shared__ float red[6];
    __shared__ float bval, bval2;
    float4 v = ((const float4*)(x + (size_t)t * DD))[tid];
    float ss = v.x * v.x + v.y * v.y + v.z * v.z + v.w * v.w;
    for (int o = 16; o; o >>= 1) ss += __shfl_down_sync(~0u, ss, o);
    if ((tid & 31) == 0) red[tid >> 5] = ss;
    __syncthreads();
    if (tid == 0) {
        float s = 0; for (int i = 0; i < 6; i++) s += red[i];
        bval = rsqrtf(s / (float)DD + EPSF);
    }
    __syncthreads();
    float rstd = bval;
    float4 w = ((const float4*)nw)[tid];
    float4 a;
    a.x = v.x * rstd * w.x; a.y = v.y * rstd * w.y;
    a.z = v.z * rstd * w.z; a.w = v.w * rstd * w.w;
    ((float4*)(g_xn + (size_t)t * DD))[tid] = a;
    float s2 = a.x * a.x + a.y * a.y + a.z * a.z + a.w * a.w;
    for (int o = 16; o; o >>= 1) s2 += __shfl_down_sync(~0u, s2, o);
    __syncthreads();
    if ((tid & 31) == 0) red[tid >> 5] = s2;
    __syncthreads();
    if (tid == 0) {
        float s = 0; for (int i = 0; i < 6; i++) s += red[i];
        bval2 = 1.f / fmaxf(sqrtf(s), EPSF);
    }
    __syncthreads();
    float rn = bval2;
    __half2 h0 = __float22half2_rn(make_float2(a.x * rn, a.y * rn));
    __half2 h1 = __float22half2_rn(make_float2(a.z * rn, a.w * rn));
    uint2 u;
    u.x = *(unsigned*)&h0; u.y = *(unsigned*)&h1;
    *(uint2*)(g_nh + (size_t)t * DD + tid * 4) = u;
}

// ---------------- K2: binit ------------------------------------------------------
__global__ void k_binit(const float* __restrict__ b1, const float* __restrict__ b2) {
    int i = blockIdx.x * 256 + threadIdx.x;
    const int N1 = BB * MM * DD;
    const int N2 = BB * MM * FF;
    if (i < N1) g_y[i] = 0.f;
    else if (i < N1 + N2) { int k = i - N1; g_hid[k] = b1[k % (MM * FF)]; }
    else { int k = i - N1 - N2; g_y2[k] = b2[k % (MM * DD)]; }
}

// ---------------- K3: logits via mma.sync.m16n8k16 (profiled, idx 3) -------------
__global__ void __launch_bounds__(128) k_logits() {
    int s0 = blockIdx.x * 128;
    int h = blockIdx.y, b = blockIdx.z;
    int tid = threadIdx.x, lane = tid & 31, wid = tid >> 5;
    __shared__ __half As[64][72];    // slots  [m][k]
    __shared__ __half Bs[128][72];   // tokens [n][k]
    for (int i = tid; i < 64 * 8; i += 128) {
        int r = i >> 3, sg = i & 7;
        *(uint4*)&As[r][sg * 8] = *(const uint4*)&g_slh[r * DD + h * HD + sg * 8];
    }
    for (int i = tid; i < 128 * 8; i += 128) {
        int r = i >> 3, sg = i & 7;
        *(uint4*)&Bs[r][sg * 8] =
            *(const uint4*)&g_nh[((size_t)(b * SS + s0 + r)) * DD + h * HD + sg * 8];
    }
    __syncthreads();
    int nb = wid * 32;
    unsigned Bf[4][4][2];
#pragma unroll
    for (int j = 0; j < 4; j++)
#pragma unroll
        for (int kk = 0; kk < 4; kk++) {
            unsigned ad = su32(&Bs[nb + j * 8 + (lane & 7)][kk * 16 + (lane & 8)]);
            asm volatile("ldmatrix.sync.aligned.m8n8.x2.shared.b16 {%0,%1}, [%2];"
                : "=r"(Bf[j][kk][0]), "=r"(Bf[j][kk][1]) : "r"(ad));
        }
    size_t lbase = (size_t)((b * HH + h) * MM) * SS + s0;
#pragma unroll
    for (int mi = 0; mi < 4; mi++) {
        unsigned Af[4][4];
#pragma unroll
        for (int kk = 0; kk < 4; kk++) {
            unsigned ad = su32(&As[mi * 16 + (lane & 15)][kk * 16 + ((lane & 16) >> 1)]);
            asm volatile("ldmatrix.sync.aligned.m8n8.x4.shared.b16 {%0,%1,%2,%3}, [%4];"
                : "=r"(Af[kk][0]), "=r"(Af[kk][1]), "=r"(Af[kk][2]), "=r"(Af[kk][3])
                : "r"(ad));
        }
#pragma unroll
        for (int j = 0; j < 4; j++) {
            float c0 = 0.f, c1 = 0.f, c2 = 0.f, c3 = 0.f;
#pragma unroll
            for (int kk = 0; kk < 4; kk++)
                asm volatile(
                    "mma.sync.aligned.m16n8k16.row.col.f32.f16.f16.f32 "
                    "{%0,%1,%2,%3}, {%4,%5,%6,%7}, {%8,%9}, {%0,%1,%2,%3};"
                    : "+f"(c0), "+f"(c1), "+f"(c2), "+f"(c3)
                    : "r"(Af[kk][0]), "r"(Af[kk][1]), "r"(Af[kk][2]), "r"(Af[kk][3]),
                      "r"(Bf[j][kk][0]), "r"(Bf[j][kk][1]));
            int m = mi * 16 + (lane >> 2);
            int n = nb + j * 8 + 2 * (lane & 3);
            __half2 lo = __float22half2_rn(make_float2(c0, c1));
            __half2 hi = __float22half2_rn(make_float2(c2, c3));
            *(__half2*)&g_lh[lbase + (size_t)m * SS + n] = lo;
            *(__half2*)&g_lh[lbase + (size_t)(m + 8) * SS + n] = hi;
        }
    }
}

// ---------------- K4: one-pass softmax stats -----------------------------------
__global__ void __launch_bounds__(128) k_stats() {
    int r = blockIdx.x, tid = threadIdx.x;
    const __half* row = g_lh + (size_t)r * SS;
    float4 raw[4];
    const float4* p = (const float4*)(row + tid * 32);
#pragma unroll
    for (int q = 0; q < 4; q++) raw[q] = p[q];
    float v[32];
#pragma unroll
    for (int q = 0; q < 4; q++) {
        const __half2* h2 = (const __half2*)&raw[q];
#pragma unroll
        for (int j = 0; j < 4; j++) {
            float2 f = __half22float2(h2[j]);
            v[q * 8 + j * 2] = f.x; v[q * 8 + j * 2 + 1] = f.y;
        }
    }
    float mx = -1e30f;
#pragma unroll
    for (int i = 0; i < 32; i++) mx = fmaxf(mx, v[i]);
    __shared__ float red[4];
    __shared__ float smxv;
    for (int o = 16; o; o >>= 1) mx = fmaxf(mx, __shfl_down_sync(~0u, mx, o));
    if ((tid & 31) == 0) red[tid >> 5] = mx;
    __syncthreads();
    if (tid == 0) smxv = fmaxf(fmaxf(red[0], red[1]), fmaxf(red[2], red[3]));
    __syncthreads();
    float gmx = smxv;
    float sm = 0.f;
#pragma unroll
    for (int i = 0; i < 32; i++) sm += __expf(v[i] - gmx);
    for (int o = 16; o; o >>= 1) sm += __shfl_down_sync(~0u, sm, o);
    __syncthreads();
    if ((tid & 31) == 0) red[tid >> 5] = sm;
    __syncthreads();
    if (tid == 0) {
        g_rmax[r] = gmx;
        g_rsum[r] = red[0] + red[1] + red[2] + red[3];
    }
}

// ---------------- K5: dispatch (round-2 proven version) ---------------------------
__global__ void __launch_bounds__(128) k_disp() {
    int ch = blockIdx.x, h = blockIdx.y, b = blockIdx.z;
    int tid = threadIdx.x;
    int sp = tid >> 6;
    int w  = tid & 63;
    int mg = w >> 4;
    int dg = w & 15;
    __shared__ float pT[64][68];
    __shared__ float xts[64][68];
    __shared__ float smax[64], sinv[64];
    if (tid < 64) {
        int r = (b * HH + h) * MM + tid;
        smax[tid] = g_rmax[r];
        sinv[tid] = 1.f / g_rsum[r];
    }
    ull accL[16], accH[16];
#pragma unroll
    for (int j = 0; j < 16; j++) { accL[j] = 0ull; accH[j] = 0ull; }
    size_t lbh = (size_t)((b * HH + h) * MM) * SS;
    for (int tile = 0; tile < 8; tile++) {
        int s0 = (ch * 8 + tile) * 64;
        __syncthreads();
        for (int i = tid; i < 64 * 32; i += 128) {
            int m = i >> 5, s2 = i & 31;
            __half2 hv = *(const __half2*)&g_lh[lbh + (size_t)m * SS + s0 + 2 * s2];
            float2 f = __half22float2(hv);
            float mmax = smax[m], minv = sinv[m];
            pT[2 * s2][m]     = __expf(f.x - mmax) * minv;
            pT[2 * s2 + 1][m] = __expf(f.y - mmax) * minv;
        }
        for (int i = tid; i < 64 * 16; i += 128) {
            int s = i >> 4, d4 = i & 15;
            *(float4*)&xts[s][d4 * 4] =
                *(const float4*)&g_xn[((size_t)(b * SS + s0 + s)) * DD + h * HD + d4 * 4];
        }
        __syncthreads();
#pragma unroll 2
        for (int s = sp; s < 64; s += 2) {
            float4 xv = *(const float4*)&xts[s][dg * 4];
            ull xlo = pk2(xv.x, xv.y), xhi = pk2(xv.z, xv.w);
#pragma unroll
            for (int j = 0; j < 4; j++) {
                float4 pv = *(const float4*)&pT[s][mg * 16 + j * 4];
                ull p0 = pk2(pv.x, pv.x), p1 = pk2(pv.y, pv.y);
                ull p2 = pk2(pv.z, pv.z), p3 = pk2(pv.w, pv.w);
                FMA2(accL[j * 4 + 0], p0, xlo); FMA2(accH[j * 4 + 0], p0, xhi);
                FMA2(accL[j * 4 + 1], p1, xlo); FMA2(accH[j * 4 + 1], p1, xhi);
                FMA2(accL[j * 4 + 2], p2, xlo); FMA2(accH[j * 4 + 2], p2, xhi);
                FMA2(accL[j * 4 + 3], p3, xlo); FMA2(accH[j * 4 + 3], p3, xhi);
            }
        }
    }
#pragma unroll
    for (int ml = 0; ml < 16; ml++) {
        int m = mg * 16 + ml;
        float a0, a1, a2, a3;
        upk2(accL[ml], a0, a1); upk2(accH[ml], a2, a3);
        float* base = &g_y[((size_t)(b * MM + m)) * DD + h * HD + dg * 4];
        atomicAdd(base + 0, a0);
        atomicAdd(base + 1, a1);
        atomicAdd(base + 2, a2);
        atomicAdd(base + 3, a3);
    }
}

// ---------------- K6: fc1 ----------------------------------------------------------
__global__ void __launch_bounds__(256) k_fc1(const float* __restrict__ w1) {
    int fblk = blockIdx.x, m = blockIdx.y, kc = blockIdx.z;
    int tid = threadIdx.x;
    int f = fblk * 1024 + tid * 4;
    __shared__ float ysT[192][12];
    for (int i = tid; i < 8 * 192; i += 256) {
        int bb = i / 192, k = i % 192;
        ysT[k][bb] = g_y[((size_t)(bb * MM + m)) * DD + kc * 192 + k];
    }
    __syncthreads();
    ull acc[4][4];
#pragma unroll
    for (int i = 0; i < 4; i++)
#pragma unroll
        for (int j = 0; j < 4; j++) acc[i][j] = 0ull;
    const float* wp = w1 + (size_t)m * DD * FF + (size_t)(kc * 192) * FF + f;
    float4 wv = *(const float4*)wp;
#pragma unroll 4
    for (int k = 0; k < 192; k++) {
        float4 wn;
        if (k < 191) wn = *(const float4*)(wp + (size_t)(k + 1) * FF);
        ulonglong2 ya = *(const ulonglong2*)&ysT[k][0];
        ulonglong2 yb = *(const ulonglong2*)&ysT[k][4];
        ull w0 = pk2(wv.x, wv.x), w1d = pk2(wv.y, wv.y);
        ull w2 = pk2(wv.z, wv.z), w3 = pk2(wv.w, wv.w);
        FMA2(acc[0][0], w0, ya.x); FMA2(acc[0][1], w0, ya.y); FMA2(acc[0][2], w0, yb.x); FMA2(acc[0][3], w0, yb.y);
        FMA2(acc[1][0], w1d, ya.x); FMA2(acc[1][1], w1d, ya.y); FMA2(acc[1][2], w1d, yb.x); FMA2(acc[1][3], w1d, yb.y);
        FMA2(acc[2][0], w2, ya.x); FMA2(acc[2][1], w2, ya.y); FMA2(acc[2][2], w2, yb.x); FMA2(acc[2][3], w2, yb.y);
        FMA2(acc[3][0], w3, ya.x); FMA2(acc[3][1], w3, ya.y); FMA2(acc[3][2], w3, yb.x); FMA2(acc[3][3], w3, yb.y);
        wv = wn;
    }
#pragma unroll
    for (int fi = 0; fi < 4; fi++)
#pragma unroll
        for (int bp = 0; bp < 4; bp++) {
            float a0, a1;
            upk2(acc[fi][bp], a0, a1);
            atomicAdd(&g_hid[((size_t)((2 * bp) * MM + m)) * FF + f + fi], a0);
            atomicAdd(&g_hid[((size_t)((2 * bp + 1) * MM + m)) * FF + f + fi], a1);
        }
}

// ---------------- K7: fc2 (gelu on load) --------------------------------------------
__global__ void __launch_bounds__(192) k_fc2(const float* __restrict__ w2) {
    int m = blockIdx.x, kc = blockIdx.y;
    int tid = threadIdx.x;
    int d = tid * 4;
    __shared__ float hsT[384][12];
    for (int i = tid; i < 8 * 384; i += 192) {
        int bb = i / 384, k = i % 384;
        float v = g_hid[((size_t)(bb * MM + m)) * FF + kc * 384 + k];
        hsT[k][bb] = 0.5f * v * (1.f + erff(v * 0.70710678118654752f));
    }
    __syncthreads();
    ull acc[4][4];
#pragma unroll
    for (int i = 0; i < 4; i++)
#pragma unroll
        for (int j = 0; j < 4; j++) acc[i][j] = 0ull;
    const float* wp = w2 + (size_t)m * FF * DD + (size_t)(kc * 384) * DD + d;
    float4 wv = *(const float4*)wp;
#pragma unroll 4
    for (int k = 0; k < 384; k++) {
        float4 wn;
        if (k < 383) wn = *(const float4*)(wp + (size_t)(k + 1) * DD);
        ulonglong2 ya = *(const ulonglong2*)&hsT[k][0];
        ulonglong2 yb = *(const ulonglong2*)&hsT[k][4];
        ull w0 = pk2(wv.x, wv.x), w1d = pk2(wv.y, wv.y);
        ull w2d = pk2(wv.z, wv.z), w3 = pk2(wv.w, wv.w);
        FMA2(acc[0][0], w0, ya.x); FMA2(acc[0][1], w0, ya.y); FMA2(acc[0][2], w0, yb.x); FMA2(acc[0][3], w0, yb.y);
        FMA2(acc[1][0], w1d, ya.x); FMA2(acc[1][1], w1d, ya.y); FMA2(acc[1][2], w1d, yb.x); FMA2(acc[1][3], w1d, yb.y);
        FMA2(acc[2][0], w2d, ya.x); FMA2(acc[2][1], w2d, ya.y); FMA2(acc[2][2], w2d, yb.x); FMA2(acc[2][3], w2d, yb.y);
        FMA2(acc[3][0], w3, ya.x); FMA2(acc[3][1], w3, ya.y); FMA2(acc[3][2], w3, yb.x); FMA2(acc[3][3], w3, yb.y);
        wv = wn;
    }
#pragma unroll
    for (int di = 0; di < 4; di++)
#pragma unroll
        for (int bp = 0; bp < 4; bp++) {
            float a0, a1;
            upk2(acc[di][bp], a0, a1);
            atomicAdd(&g_y2[((size_t)((2 * bp) * MM + m)) * DD + d + di], a0);
            atomicAdd(&g_y2[((size_t)((2 * bp + 1) * MM + m)) * DD + d + di], a1);
        }
}

// ---------------- K8: combine (round-2 proven version) -----------------------------
__global__ void __launch_bounds__(128) k_comb(float* __restrict__ out) {
    int sb = blockIdx.x, h = blockIdx.y, b = blockIdx.z;
    int s0 = sb * 64;
    int tid = threadIdx.x;
    __shared__ float pSm[64][68];
    __shared__ float y2s[64][72];
    __shared__ float pmax[2][64], psum[2][64], smx[64], sinvs[64];
    size_t lbh = (size_t)((b * HH + h) * MM) * SS;
    for (int i = tid; i < 64 * 32; i += 128) {
        int m = i >> 5, s2 = i & 31;
        __half2 hv = *(const __half2*)&g_lh[lbh + (size_t)m * SS + s0 + 2 * s2];
        float2 f = __half22float2(hv);
        pSm[m][2 * s2] = f.x; pSm[m][2 * s2 + 1] = f.y;
    }
    for (int i = tid; i < 64 * 16; i += 128) {
        int m = i >> 4, d4 = i & 15;
        *(float4*)&y2s[m][d4 * 4] =
            *(const float4*)&g_y2[((size_t)(b * MM + m)) * DD + h * HD + d4 * 4];
    }
    __syncthreads();
    {
        int t = tid & 63, mh = tid >> 6;
        float mx = -1e30f;
#pragma unroll 8
        for (int mm = 0; mm < 32; mm++) mx = fmaxf(mx, pSm[mh * 32 + mm][t]);
        pmax[mh][t] = mx;
    }
    __syncthreads();
    if (tid < 64) smx[tid] = fmaxf(pmax[0][tid], pmax[1][tid]);
    __syncthreads();
    {
        int t = tid & 63, mh = tid >> 6;
        float mx = smx[t], sm = 0.f;
#pragma unroll 8
        for (int mm = 0; mm < 32; mm++) {
            float e = __expf(pSm[mh * 32 + mm][t] - mx);
            pSm[mh * 32 + mm][t] = e;
            sm += e;
        }
        psum[mh][t] = sm;
    }
    __syncthreads();
    if (tid < 64) sinvs[tid] = 1.f / (psum[0][tid] + psum[1][tid]);
    __syncthreads();
    int sg = tid >> 3, dgrp = tid & 7;
    ull acc[4][4];
#pragma unroll
    for (int i = 0; i < 4; i++)
#pragma unroll
        for (int j = 0; j < 4; j++) acc[i][j] = 0ull;
#pragma unroll 4
    for (int m = 0; m < 64; m++) {
        float4 pa = *(const float4*)&pSm[m][sg * 4];
        ull pd0 = pk2(pa.x, pa.x), pd1 = pk2(pa.y, pa.y);
        ull pd2 = pk2(pa.z, pa.z), pd3 = pk2(pa.w, pa.w);
        ulonglong2 yva = *(const ulonglong2*)&y2s[m][dgrp * 8];
        ulonglong2 yvb = *(const ulonglong2*)&y2s[m][dgrp * 8 + 4];
        FMA2(acc[0][0], pd0, yva.x); FMA2(acc[0][1], pd0, yva.y); FMA2(acc[0][2], pd0, yvb.x); FMA2(acc[0][3], pd0, yvb.y);
        FMA2(acc[1][0], pd1, yva.x); FMA2(acc[1][1], pd1, yva.y); FMA2(acc[1][2], pd1, yvb.x); FMA2(acc[1][3], pd1, yvb.y);
        FMA2(acc[2][0], pd2, yva.x); FMA2(acc[2][1], pd2, yva.y); FMA2(acc[2][2], pd2, yvb.x); FMA2(acc[2][3], pd2, yvb.y);
        FMA2(acc[3][0], pd3, yva.x); FMA2(acc[3][1], pd3, yva.y); FMA2(acc[3][2], pd3, yvb.x); FMA2(acc[3][3], pd3, yvb.y);
    }
#pragma unroll
    for (int ss = 0; ss < 4; ss++) {
        int s = s0 + sg * 4 + ss;
        float inv = sinvs[sg * 4 + ss];
        float o0, o1, o2, o3, o4, o5, o6, o7;
        upk2(acc[ss][0], o0, o1); upk2(acc[ss][1], o2, o3);
        upk2(acc[ss][2], o4, o5); upk2(acc[ss][3], o6, o7);
        float* op = &out[((size_t)(b * SS + s)) * DD + h * HD + dgrp * 8];
        *(float4*)(op + 0) = make_float4(o0 * inv, o1 * inv, o2 * inv, o3 * inv);
        *(float4*)(op + 4) = make_float4(o4 * inv, o5 * inv, o6 * inv, o7 * inv);
    }
}

// ---------------- launch --------------------------------------------------------
extern "C" void kernel_launch(void* const* d_in, const int* in_sizes, int n_in,
                              void* d_out, int out_size) {
    const float* x      = (const float*)d_in[0];
    const float* slots  = (const float*)d_in[1];
    const float* scale  = (const float*)d_in[2];
    const float* fc1_w  = (const float*)d_in[3];
    const float* fc1_b  = (const float*)d_in[4];
    const float* fc2_w  = (const float*)d_in[5];
    const float* fc2_b  = (const float*)d_in[6];
    const float* norm_w = (const float*)d_in[7];
    float* out = (float*)d_out;

    k_slots<<<MM, 256>>>(slots, scale);                                   // idx 0
    k_norm<<<BB * SS, 192>>>(x, norm_w);                                  // idx 1
    k_binit<<<(BB * MM * (2 * DD + FF)) / 256, 256>>>(fc1_b, fc2_b);      // idx 2
    k_logits<<<dim3(SS / 128, HH, BB), 128>>>();                          // idx 3 (profiled)
    k_stats<<<BB * HH * MM, 128>>>();                                     // idx 4
    k_disp<<<dim3(8, HH, BB), 128>>>();                                   // idx 5
    k_fc1<<<dim3(3, MM, 4), 256>>>(fc1_w);                                // idx 6
    k_fc2<<<dim3(MM, 8), 192>>>(fc2_w);                                   // idx 7
    k_comb<<<dim3(SS / 64, HH, BB), 128>>>(out);                          // idx 8
}

// round 8
// speedup vs baseline: 1.6192x; 1.3516x over previous
#include <cuda_runtime.h>
#include <cuda_fp16.h>
#include <math.h>

#define BB 8
#define SS 4096
#define DD 768
#define MM 64
#define FF 3072
#define HH 12
#define HD 64
#define EPSF 1e-5f

typedef unsigned long long ull;

__device__ __forceinline__ ull pk2(float lo, float hi) {
    ull r;
    asm("mov.b64 %0, {%1, %2};" : "=l"(r) : "f"(lo), "f"(hi));
    return r;
}
__device__ __forceinline__ void upk2(ull v, float& lo, float& hi) {
    asm("mov.b64 {%0, %1}, %2;" : "=f"(lo), "=f"(hi) : "l"(v));
}
#define FMA2(a, x, y) asm("fma.rn.f32x2 %0, %1, %2, %0;" : "+l"(a) : "l"(x), "l"(y))

__device__ __forceinline__ unsigned su32(const void* p) {
    return (unsigned)__cvta_generic_to_shared(p);
}

#define MMA16816(c, A, b0, b1) \
    asm volatile("mma.sync.aligned.m16n8k16.row.col.f32.f16.f16.f32 " \
        "{%0,%1,%2,%3}, {%4,%5,%6,%7}, {%8,%9}, {%0,%1,%2,%3};" \
        : "+f"((c)[0]), "+f"((c)[1]), "+f"((c)[2]), "+f"((c)[3]) \
        : "r"((A)[0]), "r"((A)[1]), "r"((A)[2]), "r"((A)[3]), "r"(b0), "r"(b1))

// ---------------- scratch -----------------------------------------------------
__device__ __half g_slh[MM * DD];               // l2norm(slots)*scale, fp16
__device__ __half g_nh[BB * SS * DD];           // l2-normalized tokens, fp16
__device__ float  g_tn[BB * SS];                // ||rms-normed token||
__device__ __half g_lh[(size_t)BB * HH * MM * SS];
__device__ float  g_rmax[BB * HH * MM];
__device__ float  g_rsum[BB * HH * MM];
__device__ float  g_y[BB * MM * DD];
__device__ float  g_hid[(size_t)BB * MM * FF];
__device__ float  g_y2[BB * MM * DD];

// ---------------- K0: slots (fp16 out) ------------------------------------------
__global__ void k_slots(const float* __restrict__ slots, const float* __restrict__ scale) {
    int m = blockIdx.x, tid = threadIdx.x;
    __shared__ float red[8];
    float ss = 0.f;
    for (int i = tid; i < DD; i += 256) { float v = slots[m * DD + i]; ss += v * v; }
    for (int o = 16; o; o >>= 1) ss += __shfl_down_sync(~0u, ss, o);
    if ((tid & 31) == 0) red[tid >> 5] = ss;
    __syncthreads();
    if (tid == 0) { float s = 0; for (int i = 0; i < 8; i++) s += red[i]; red[0] = s; }
    __syncthreads();
    float inv = scale[m] / fmaxf(sqrtf(red[0]), EPSF);
    for (int i = tid; i < DD; i += 256) g_slh[m * DD + i] = __float2half(slots[m * DD + i] * inv);
}

// ---------------- K1: rmsnorm -> nh fp16 + token norm ----------------------------
__global__ void k_norm(const float* __restrict__ x, const float* __restrict__ nw) {
    int t = blockIdx.x, tid = threadIdx.x;
    __shared__ float red[6];
    __shared__ float bval, bval2;
    float4 v = ((const float4*)(x + (size_t)t * DD))[tid];
    float ss = v.x * v.x + v.y * v.y + v.z * v.z + v.w * v.w;
    for (int o = 16; o; o >>= 1) ss += __shfl_down_sync(~0u, ss, o);
    if ((tid & 31) == 0) red[tid >> 5] = ss;
    __syncthreads();
    if (tid == 0) {
        float s = 0; for (int i = 0; i < 6; i++) s += red[i];
        bval = rsqrtf(s / (float)DD + EPSF);
    }
    __syncthreads();
    float rstd = bval;
    float4 w = ((const float4*)nw)[tid];
    float4 a;
    a.x = v.x * rstd * w.x; a.y = v.y * rstd * w.y;
    a.z = v.z * rstd * w.z; a.w = v.w * rstd * w.w;
    float s2 = a.x * a.x + a.y * a.y + a.z * a.z + a.w * a.w;
    for (int o = 16; o; o >>= 1) s2 += __shfl_down_sync(~0u, s2, o);
    if ((tid & 31) == 0) red[tid >> 5] = s2;
    __syncthreads();
    if (tid == 0) {
        float s = 0; for (int i = 0; i < 6; i++) s += red[i];
        float tnv = fmaxf(sqrtf(s), EPSF);
        g_tn[t] = tnv;
        bval2 = 1.f / tnv;
    }
    __syncthreads();
    float rn = bval2;
    __half2 h0 = __float22half2_rn(make_float2(a.x * rn, a.y * rn));
    __half2 h1 = __float22half2_rn(make_float2(a.z * rn, a.w * rn));
    uint2 u;
    u.x = *(unsigned*)&h0; u.y = *(unsigned*)&h1;
    *(uint2*)(g_nh + (size_t)t * DD + tid * 4) = u;
}

// ---------------- K2: binit ------------------------------------------------------
__global__ void k_binit(const float* __restrict__ b1, const float* __restrict__ b2) {
    int i = blockIdx.x * 256 + threadIdx.x;
    const int N1 = BB * MM * DD;
    const int N2 = BB * MM * FF;
    if (i < N1) g_y[i] = 0.f;
    else if (i < N1 + N2) { int k = i - N1; g_hid[k] = b1[k % (MM * FF)]; }
    else { int k = i - N1 - N2; g_y2[k] = b2[k % (MM * DD)]; }
}

// ---------------- K3: logits via mma (proven round 7; idx 3 profiled) -------------
__global__ void __launch_bounds__(128) k_logits() {
    int s0 = blockIdx.x * 128;
    int h = blockIdx.y, b = blockIdx.z;
    int tid = threadIdx.x, lane = tid & 31, wid = tid >> 5;
    __shared__ __half As[64][72];    // slots  [m][k]
    __shared__ __half Bs[128][72];   // tokens [n][k]
    for (int i = tid; i < 64 * 8; i += 128) {
        int r = i >> 3, sg = i & 7;
        *(uint4*)&As[r][sg * 8] = *(const uint4*)&g_slh[r * DD + h * HD + sg * 8];
    }
    for (int i = tid; i < 128 * 8; i += 128) {
        int r = i >> 3, sg = i & 7;
        *(uint4*)&Bs[r][sg * 8] =
            *(const uint4*)&g_nh[((size_t)(b * SS + s0 + r)) * DD + h * HD + sg * 8];
    }
    __syncthreads();
    int nb = wid * 32;
    unsigned Bf[4][4][2];
#pragma unroll
    for (int j = 0; j < 4; j++)
#pragma unroll
        for (int kk = 0; kk < 4; kk++) {
            unsigned ad = su32(&Bs[nb + j * 8 + (lane & 7)][kk * 16 + (lane & 8)]);
            asm volatile("ldmatrix.sync.aligned.m8n8.x2.shared.b16 {%0,%1}, [%2];"
                : "=r"(Bf[j][kk][0]), "=r"(Bf[j][kk][1]) : "r"(ad));
        }
    size_t lbase = (size_t)((b * HH + h) * MM) * SS + s0;
#pragma unroll
    for (int mi = 0; mi < 4; mi++) {
        unsigned Af[4][4];
#pragma unroll
        for (int kk = 0; kk < 4; kk++) {
            unsigned ad = su32(&As[mi * 16 + (lane & 15)][kk * 16 + ((lane & 16) >> 1)]);
            asm volatile("ldmatrix.sync.aligned.m8n8.x4.shared.b16 {%0,%1,%2,%3}, [%4];"
                : "=r"(Af[kk][0]), "=r"(Af[kk][1]), "=r"(Af[kk][2]), "=r"(Af[kk][3])
                : "r"(ad));
        }
#pragma unroll
        for (int j = 0; j < 4; j++) {
            float c[4] = {0.f, 0.f, 0.f, 0.f};
#pragma unroll
            for (int kk = 0; kk < 4; kk++)
                MMA16816(c, Af[kk], Bf[j][kk][0], Bf[j][kk][1]);
            int m = mi * 16 + (lane >> 2);
            int n = nb + j * 8 + 2 * (lane & 3);
            __half2 lo = __float22half2_rn(make_float2(c[0], c[1]));
            __half2 hi = __float22half2_rn(make_float2(c[2], c[3]));
            *(__half2*)&g_lh[lbase + (size_t)m * SS + n] = lo;
            *(__half2*)&g_lh[lbase + (size_t)(m + 8) * SS + n] = hi;
        }
    }
}

// ---------------- K4: one-pass softmax stats -----------------------------------
__global__ void __launch_bounds__(128) k_stats() {
    int r = blockIdx.x, tid = threadIdx.x;
    const __half* row = g_lh + (size_t)r * SS;
    float4 raw[4];
    const float4* p = (const float4*)(row + tid * 32);
#pragma unroll
    for (int q = 0; q < 4; q++) raw[q] = p[q];
    float v[32];
#pragma unroll
    for (int q = 0; q < 4; q++) {
        const __half2* h2 = (const __half2*)&raw[q];
#pragma unroll
        for (int j = 0; j < 4; j++) {
            float2 f = __half22float2(h2[j]);
            v[q * 8 + j * 2] = f.x; v[q * 8 + j * 2 + 1] = f.y;
        }
    }
    float mx = -1e30f;
#pragma unroll
    for (int i = 0; i < 32; i++) mx = fmaxf(mx, v[i]);
    __shared__ float red[4];
    __shared__ float smxv;
    for (int o = 16; o; o >>= 1) mx = fmaxf(mx, __shfl_down_sync(~0u, mx, o));
    if ((tid & 31) == 0) red[tid >> 5] = mx;
    __syncthreads();
    if (tid == 0) smxv = fmaxf(fmaxf(red[0], red[1]), fmaxf(red[2], red[3]));
    __syncthreads();
    float gmx = smxv;
    float sm = 0.f;
#pragma unroll
    for (int i = 0; i < 32; i++) sm += __expf(v[i] - gmx);
    for (int o = 16; o; o >>= 1) sm += __shfl_down_sync(~0u, sm, o);
    __syncthreads();
    if ((tid & 31) == 0) red[tid >> 5] = sm;
    __syncthreads();
    if (tid == 0) {
        g_rmax[r] = gmx;
        g_rsum[r] = red[0] + red[1] + red[2] + red[3];
    }
}

// ---------------- K5: dispatch via mma --------------------------------------------
// y[m,d] += sum_s (p[m,s]*||x_s||) * nh[s,d]
__global__ void __launch_bounds__(128) k_disp() {
    int ch = blockIdx.x, h = blockIdx.y, b = blockIdx.z;
    int tid = threadIdx.x, lane = tid & 31, wid = tid >> 5;
    __shared__ __half As[64][72];   // [m][s]  folded probs
    __shared__ __half Bs[64][72];   // [s][d]  nh
    __shared__ float smax[64], sinv[64], tns[512];
    if (tid < 64) {
        int r = (b * HH + h) * MM + tid;
        smax[tid] = g_rmax[r];
        sinv[tid] = 1.f / g_rsum[r];
    }
    for (int u = tid; u < 512; u += 128) tns[u] = g_tn[b * SS + ch * 512 + u];
    float acc[4][2][4];
#pragma unroll
    for (int i = 0; i < 4; i++)
#pragma unroll
        for (int j = 0; j < 2; j++)
#pragma unroll
            for (int q = 0; q < 4; q++) acc[i][j][q] = 0.f;
    size_t lbh = (size_t)((b * HH + h) * MM) * SS;
    int nb = wid * 16;
    __syncthreads();
    for (int tile = 0; tile < 8; tile++) {
        int s0 = ch * 512 + tile * 64;
        if (tile) __syncthreads();
        for (int u = tid; u < 512; u += 128) {
            int m = u >> 3, q = u & 7;
            uint4 raw = *(const uint4*)&g_lh[lbh + (size_t)m * SS + s0 + q * 8];
            const __half2* h2 = (const __half2*)&raw;
            float mm = smax[m], iv = sinv[m];
            const float* tp = &tns[tile * 64 + q * 8];
            __half2 outh[4];
#pragma unroll
            for (int j = 0; j < 4; j++) {
                float2 f = __half22float2(h2[j]);
                float e0 = __expf(f.x - mm) * iv * tp[2 * j];
                float e1 = __expf(f.y - mm) * iv * tp[2 * j + 1];
                outh[j] = __float22half2_rn(make_float2(e0, e1));
            }
            *(uint4*)&As[m][q * 8] = *(uint4*)outh;
        }
        for (int u = tid; u < 512; u += 128) {
            int s = u >> 3, q = u & 7;
            *(uint4*)&Bs[s][q * 8] =
                *(const uint4*)&g_nh[((size_t)(b * SS + s0 + s)) * DD + h * HD + q * 8];
        }
        __syncthreads();
#pragma unroll
        for (int kk = 0; kk < 4; kk++) {
            unsigned Af[4][4];
#pragma unroll
            for (int mi = 0; mi < 4; mi++) {
                unsigned ad = su32(&As[mi * 16 + (lane & 15)][kk * 16 + ((lane & 16) >> 1)]);
                asm volatile("ldmatrix.sync.aligned.m8n8.x4.shared.b16 {%0,%1,%2,%3}, [%4];"
                    : "=r"(Af[mi][0]), "=r"(Af[mi][1]), "=r"(Af[mi][2]), "=r"(Af[mi][3])
                    : "r"(ad));
            }
            unsigned Bf[4];
            {
                unsigned ad = su32(&Bs[kk * 16 + ((lane >> 3) & 1) * 8 + (lane & 7)]
                                     [nb + ((lane >> 4) & 1) * 8]);
                asm volatile("ldmatrix.sync.aligned.m8n8.x4.trans.shared.b16 {%0,%1,%2,%3}, [%4];"
                    : "=r"(Bf[0]), "=r"(Bf[1]), "=r"(Bf[2]), "=r"(Bf[3]) : "r"(ad));
            }
#pragma unroll
            for (int mi = 0; mi < 4; mi++) {
                MMA16816(acc[mi][0], Af[mi], Bf[0], Bf[1]);
                MMA16816(acc[mi][1], Af[mi], Bf[2], Bf[3]);
            }
        }
    }
#pragma unroll
    for (int mi = 0; mi < 4; mi++) {
        int m = mi * 16 + (lane >> 2);
#pragma unroll
        for (int nj = 0; nj < 2; nj++) {
            int d = nb + nj * 8 + 2 * (lane & 3);
            float* bp = &g_y[((size_t)(b * MM + m)) * DD + h * HD + d];
            atomicAdd(bp, acc[mi][nj][0]);
            atomicAdd(bp + 1, acc[mi][nj][1]);
            atomicAdd(bp + 8 * DD, acc[mi][nj][2]);
            atomicAdd(bp + 8 * DD + 1, acc[mi][nj][3]);
        }
    }
}

// ---------------- K6: fc1 (proven) --------------------------------------------------
__global__ void __launch_bounds__(256) k_fc1(const float* __restrict__ w1) {
    int fblk = blockIdx.x, m = blockIdx.y, kc = blockIdx.z;
    int tid = threadIdx.x;
    int f = fblk * 1024 + tid * 4;
    __shared__ float ysT[192][12];
    for (int i = tid; i < 8 * 192; i += 256) {
        int bb = i / 192, k = i % 192;
        ysT[k][bb] = g_y[((size_t)(bb * MM + m)) * DD + kc * 192 + k];
    }
    __syncthreads();
    ull acc[4][4];
#pragma unroll
    for (int i = 0; i < 4; i++)
#pragma unroll
        for (int j = 0; j < 4; j++) acc[i][j] = 0ull;
    const float* wp = w1 + (size_t)m * DD * FF + (size_t)(kc * 192) * FF + f;
    float4 wv = *(const float4*)wp;
#pragma unroll 4
    for (int k = 0; k < 192; k++) {
        float4 wn;
        if (k < 191) wn = *(const float4*)(wp + (size_t)(k + 1) * FF);
        ulonglong2 ya = *(const ulonglong2*)&ysT[k][0];
        ulonglong2 yb = *(const ulonglong2*)&ysT[k][4];
        ull w0 = pk2(wv.x, wv.x), w1d = pk2(wv.y, wv.y);
        ull w2 = pk2(wv.z, wv.z), w3 = pk2(wv.w, wv.w);
        FMA2(acc[0][0], w0, ya.x); FMA2(acc[0][1], w0, ya.y); FMA2(acc[0][2], w0, yb.x); FMA2(acc[0][3], w0, yb.y);
        FMA2(acc[1][0], w1d, ya.x); FMA2(acc[1][1], w1d, ya.y); FMA2(acc[1][2], w1d, yb.x); FMA2(acc[1][3], w1d, yb.y);
        FMA2(acc[2][0], w2, ya.x); FMA2(acc[2][1], w2, ya.y); FMA2(acc[2][2], w2, yb.x); FMA2(acc[2][3], w2, yb.y);
        FMA2(acc[3][0], w3, ya.x); FMA2(acc[3][1], w3, ya.y); FMA2(acc[3][2], w3, yb.x); FMA2(acc[3][3], w3, yb.y);
        wv = wn;
    }
#pragma unroll
    for (int fi = 0; fi < 4; fi++)
#pragma unroll
        for (int bp = 0; bp < 4; bp++) {
            float a0, a1;
            upk2(acc[fi][bp], a0, a1);
            atomicAdd(&g_hid[((size_t)((2 * bp) * MM + m)) * FF + f + fi], a0);
            atomicAdd(&g_hid[((size_t)((2 * bp + 1) * MM + m)) * FF + f + fi], a1);
        }
}

// ---------------- K7: fc2 (gelu on load, proven) -------------------------------------
__global__ void __launch_bounds__(192) k_fc2(const float* __restrict__ w2) {
    int m = blockIdx.x, kc = blockIdx.y;
    int tid = threadIdx.x;
    int d = tid * 4;
    __shared__ float hsT[384][12];
    for (int i = tid; i < 8 * 384; i += 192) {
        int bb = i / 384, k = i % 384;
        float v = g_hid[((size_t)(bb * MM + m)) * FF + kc * 384 + k];
        hsT[k][bb] = 0.5f * v * (1.f + erff(v * 0.70710678118654752f));
    }
    __syncthreads();
    ull acc[4][4];
#pragma unroll
    for (int i = 0; i < 4; i++)
#pragma unroll
        for (int j = 0; j < 4; j++) acc[i][j] = 0ull;
    const float* wp = w2 + (size_t)m * FF * DD + (size_t)(kc * 384) * DD + d;
    float4 wv = *(const float4*)wp;
#pragma unroll 4
    for (int k = 0; k < 384; k++) {
        float4 wn;
        if (k < 383) wn = *(const float4*)(wp + (size_t)(k + 1) * DD);
        ulonglong2 ya = *(const ulonglong2*)&hsT[k][0];
        ulonglong2 yb = *(const ulonglong2*)&hsT[k][4];
        ull w0 = pk2(wv.x, wv.x), w1d = pk2(wv.y, wv.y);
        ull w2d = pk2(wv.z, wv.z), w3 = pk2(wv.w, wv.w);
        FMA2(acc[0][0], w0, ya.x); FMA2(acc[0][1], w0, ya.y); FMA2(acc[0][2], w0, yb.x); FMA2(acc[0][3], w0, yb.y);
        FMA2(acc[1][0], w1d, ya.x); FMA2(acc[1][1], w1d, ya.y); FMA2(acc[1][2], w1d, yb.x); FMA2(acc[1][3], w1d, yb.y);
        FMA2(acc[2][0], w2d, ya.x); FMA2(acc[2][1], w2d, ya.y); FMA2(acc[2][2], w2d, yb.x); FMA2(acc[2][3], w2d, yb.y);
        FMA2(acc[3][0], w3, ya.x); FMA2(acc[3][1], w3, ya.y); FMA2(acc[3][2], w3, yb.x); FMA2(acc[3][3], w3, yb.y);
        wv = wn;
    }
#pragma unroll
    for (int di = 0; di < 4; di++)
#pragma unroll
        for (int bp = 0; bp < 4; bp++) {
            float a0, a1;
            upk2(acc[di][bp], a0, a1);
            atomicAdd(&g_y2[((size_t)((2 * bp) * MM + m)) * DD + d + di], a0);
            atomicAdd(&g_y2[((size_t)((2 * bp + 1) * MM + m)) * DD + d + di], a1);
        }
}

// ---------------- K8: combine via mma -----------------------------------------------
// out[s,d] = (1/sum_m e[s,m]) * sum_m e[s,m] * y2[m,d]
__global__ void __launch_bounds__(128) k_comb(float* __restrict__ out) {
    int sb = blockIdx.x, h = blockIdx.y, b = blockIdx.z;
    int s0 = sb * 128;
    int tid = threadIdx.x, lane = tid & 31, w = tid >> 5;
    __shared__ __half As[64][136];   // [m][s] logits -> exp
    __shared__ __half Bs[64][72];    // [m][d] y2 fp16
    __shared__ float sinvs[128];
    size_t lbh = (size_t)((b * HH + h) * MM) * SS;
    for (int u = tid; u < 1024; u += 128) {
        int m = u >> 4, q = u & 15;
        *(uint4*)&As[m][q * 8] = *(const uint4*)&g_lh[lbh + (size_t)m * SS + s0 + q * 8];
    }
    for (int u = tid; u < 1024; u += 128) {
        int m = u >> 4, q = u & 15;
        float4 v = *(const float4*)&g_y2[((size_t)(b * MM + m)) * DD + h * HD + q * 4];
        __half2 h0 = __float22half2_rn(make_float2(v.x, v.y));
        __half2 h1 = __float22half2_rn(make_float2(v.z, v.w));
        uint2 st;
        st.x = *(unsigned*)&h0; st.y = *(unsigned*)&h1;
        *(uint2*)&Bs[m][q * 4] = st;
    }
    __syncthreads();
    // per-token softmax over m (in place, column tid of As)
    {
        float vals[64];
        float mx = -1e30f;
#pragma unroll
        for (int m = 0; m < 64; m++) {
            vals[m] = __half2float(As[m][tid]);
            mx = fmaxf(mx, vals[m]);
        }
        float sm = 0.f;
#pragma unroll
        for (int m = 0; m < 64; m++) {
            float e = __expf(vals[m] - mx);
            sm += e;
            As[m][tid] = __float2half(e);
        }
        sinvs[tid] = 1.f / sm;
    }
    __syncthreads();
    float acc[2][8][4];
#pragma unroll
    for (int i = 0; i < 2; i++)
#pragma unroll
        for (int j = 0; j < 8; j++)
#pragma unroll
            for (int q = 0; q < 4; q++) acc[i][j][q] = 0.f;
#pragma unroll
    for (int kk = 0; kk < 4; kk++) {
        unsigned Af[2][4];
#pragma unroll
        for (int mi2 = 0; mi2 < 2; mi2++) {
            int M0 = w * 32 + mi2 * 16;
            unsigned ad = su32(&As[kk * 16 + ((lane >> 4) & 1) * 8 + (lane & 7)]
                                 [M0 + ((lane >> 3) & 1) * 8]);
            asm volatile("ldmatrix.sync.aligned.m8n8.x4.trans.shared.b16 {%0,%1,%2,%3}, [%4];"
                : "=r"(Af[mi2][0]), "=r"(Af[mi2][1]), "=r"(Af[mi2][2]), "=r"(Af[mi2][3])
                : "r"(ad));
        }
        unsigned Bf[4][4];
#pragma unroll
        for (int p = 0; p < 4; p++) {
            unsigned ad = su32(&Bs[kk * 16 + ((lane >> 3) & 1) * 8 + (lane & 7)]
                                 [p * 16 + ((lane >> 4) & 1) * 8]);
            asm volatile("ldmatrix.sync.aligned.m8n8.x4.trans.shared.b16 {%0,%1,%2,%3}, [%4];"
                : "=r"(Bf[p][0]), "=r"(Bf[p][1]), "=r"(Bf[p][2]), "=r"(Bf[p][3])
                : "r"(ad));
        }
#pragma unroll
        for (int mi2 = 0; mi2 < 2; mi2++)
#pragma unroll
            for (int nj = 0; nj < 8; nj++)
                MMA16816(acc[mi2][nj], Af[mi2], Bf[nj >> 1][(nj & 1) * 2], Bf[nj >> 1][(nj & 1) * 2 + 1]);
    }
#pragma unroll
    for (int mi2 = 0; mi2 < 2; mi2++) {
        int srow = w * 32 + mi2 * 16 + (lane >> 2);
        float inv0 = sinvs[srow], inv1 = sinvs[srow + 8];
        float* o0 = &out[((size_t)(b * SS + s0 + srow)) * DD + h * HD];
        float* o1 = o0 + (size_t)8 * DD;
#pragma unroll
        for (int nj = 0; nj < 8; nj++) {
            int d = nj * 8 + 2 * (lane & 3);
            float2 v0 = make_float2(acc[mi2][nj][0] * inv0, acc[mi2][nj][1] * inv0);
            float2 v1 = make_float2(acc[mi2][nj][2] * inv1, acc[mi2][nj][3] * inv1);
            *(float2*)&o0[d] = v0;
            *(float2*)&o1[d] = v1;
        }
    }
}

// ---------------- launch --------------------------------------------------------
extern "C" void kernel_launch(void* const* d_in, const int* in_sizes, int n_in,
                              void* d_out, int out_size) {
    const float* x      = (const float*)d_in[0];
    const float* slots  = (const float*)d_in[1];
    const float* scale  = (const float*)d_in[2];
    const float* fc1_w  = (const float*)d_in[3];
    const float* fc1_b  = (const float*)d_in[4];
    const float* fc2_w  = (const float*)d_in[5];
    const float* fc2_b  = (const float*)d_in[6];
    const float* norm_w = (const float*)d_in[7];
    float* out = (float*)d_out;

    k_slots<<<MM, 256>>>(slots, scale);                                   // idx 0
    k_norm<<<BB * SS, 192>>>(x, norm_w);                                  // idx 1
    k_binit<<<(BB * MM * (2 * DD + FF)) / 256, 256>>>(fc1_b, fc2_b);      // idx 2
    k_logits<<<dim3(SS / 128, HH, BB), 128>>>();                          // idx 3 (profiled)
    k_stats<<<BB * HH * MM, 128>>>();                                     // idx 4
    k_disp<<<dim3(8, HH, BB), 128>>>();                                   // idx 5
    k_fc1<<<dim3(3, MM, 4), 256>>>(fc1_w);                                // idx 6
    k_fc2<<<dim3(MM, 8), 192>>>(fc2_w);                                   // idx 7
    k_comb<<<dim3(SS / 128, HH, BB), 128>>>(out);                         // idx 8
}